// round 2
// baseline (speedup 1.0000x reference)
#include <cuda_runtime.h>
#include <cuda_bf16.h>
#include <math.h>

// Problem constants (fixed by the reference)
#define BATCH 2
#define DGRID 128
#define DOUT  123          // 128 - 6 + 1
#define KC    6            // composed kernel extent
#define CIN   3
#define COUT  3

// Conv tiling
#define TX 32
#define TY 8
#define TZ 4
#define RX 8               // outputs per thread along x
#define BX 4               // threads in x (BX*RX = TX)
#define NTHREADS (BX*TY*TZ)   // 128

// smem input tile: (TZ+5) x (TY+5) x (TX+5) voxels x 3 ch (channel-interleaved)
#define SZ (TZ+5)          // 9
#define SY (TY+5)          // 13
#define SXV (TX+5)         // 37 voxels
#define SXF (SXV*3)        // 111 floats per (z,y) row
#define SPLANE (SY*SXF)    // 1443
#define SIN_FLOATS (SZ*SPLANE)  // 12987
#define SIN_PAD (SIN_FLOATS + 1) // pad to even -> weight pairs 8B aligned
#define NW (KC*KC*KC*CIN*COUT)  // 1944 composed weights
#define SMEM_FLOATS (SIN_PAD + 2*NW)   // weights stored as {w,w} pairs

// ---------------- device scratch (static allocation — allowed) ----------------
__device__ float g_dense[(size_t)BATCH * DGRID * DGRID * DGRID * 3];   // ~50.3 MB
__device__ float g_w12[4*4*4*3*5];   // W1 (*) W2 : 4^3, 3 -> 5
__device__ float g_wc[NW];           // composed 6^3, 3 -> 3; layout [tap][cin][cout]

// ---------------- f32x2 helpers ----------------
__device__ __forceinline__ unsigned long long ffma2(unsigned long long a,
                                                    unsigned long long b,
                                                    unsigned long long c) {
    unsigned long long d;
    asm("fma.rn.f32x2 %0, %1, %2, %3;" : "=l"(d) : "l"(a), "l"(b), "l"(c));
    return d;
}
__device__ __forceinline__ unsigned long long packf2(float lo, float hi) {
    unsigned long long d;
    asm("mov.b64 %0, {%1, %2};" : "=l"(d) : "f"(lo), "f"(hi));
    return d;
}
__device__ __forceinline__ void unpackf2(unsigned long long v, float& lo, float& hi) {
    asm("mov.b64 {%0, %1}, %2;" : "=f"(lo), "=f"(hi) : "l"(v));
}

// ---------------- weight composition ----------------
__global__ void compose_w12_kernel(const float* __restrict__ W1,
                                   const float* __restrict__ W2) {
    int idx = blockIdx.x * blockDim.x + threadIdx.x;
    if (idx >= 4*4*4*3*5) return;
    int c5 = idx % 5; int t = idx / 5;
    int ci = t % 3;   t /= 3;
    int kx = t % 4;   t /= 4;
    int ky = t % 4;   int kz = t / 4;
    float s = 0.f;
    for (int az = 0; az < 2; az++) {
        int bz = kz - az; if (bz < 0 || bz > 2) continue;
        for (int ay = 0; ay < 2; ay++) {
            int by = ky - ay; if (by < 0 || by > 2) continue;
            for (int ax = 0; ax < 2; ax++) {
                int bx = kx - ax; if (bx < 0 || bx > 2) continue;
                const float* w1 = W1 + (((az*2 + ay)*2 + ax)*3 + ci)*9;
                const float* w2 = W2 + ((bz*3 + by)*3 + bx)*9*5;
                #pragma unroll
                for (int m = 0; m < 9; m++)
                    s += w1[m] * w2[m*5 + c5];
            }
        }
    }
    g_w12[idx] = s;
}

__global__ void compose_wc_kernel(const float* __restrict__ W3) {
    int idx = blockIdx.x * blockDim.x + threadIdx.x;
    if (idx >= NW) return;
    int co = idx % 3; int t = idx / 3;
    int ci = t % 3;   t /= 3;
    int kx = t % 6;   t /= 6;
    int ky = t % 6;   int kz = t / 6;
    float s = 0.f;
    for (int dz = 0; dz < 4; dz++) {
        int ez = kz - dz; if (ez < 0 || ez > 2) continue;
        for (int dy = 0; dy < 4; dy++) {
            int ey = ky - dy; if (ey < 0 || ey > 2) continue;
            for (int dx = 0; dx < 4; dx++) {
                int ex = kx - dx; if (ex < 0 || ex > 2) continue;
                const float* w12 = g_w12 + (((dz*4 + dy)*4 + dx)*3 + ci)*5;
                const float* w3  = W3 + ((ez*3 + ey)*3 + ex)*5*3;
                #pragma unroll
                for (int c5 = 0; c5 < 5; c5++)
                    s += w12[c5] * w3[c5*3 + co];
            }
        }
    }
    g_wc[idx] = s;
}

// ---------------- scatter ----------------
__global__ void scatter_kernel(const int* __restrict__ coords,
                               const float* __restrict__ voxels, int n) {
    int i = blockIdx.x * blockDim.x + threadIdx.x;
    if (i >= n) return;
    int b = coords[4*i + 0];
    int z = coords[4*i + 1];
    int y = coords[4*i + 2];
    int x = coords[4*i + 3];
    size_t base = ((((size_t)b*DGRID + z)*DGRID + y)*DGRID + x) * 3;
    atomicAdd(&g_dense[base + 0], voxels[3*i + 0]);
    atomicAdd(&g_dense[base + 1], voxels[3*i + 1]);
    atomicAdd(&g_dense[base + 2], voxels[3*i + 2]);
}

// ---------------- fused 6x6x6 conv + bias + relu (FFMA2 mainloop) ----------------
__global__ __launch_bounds__(NTHREADS, 3)
void conv6_kernel(const float* __restrict__ b3, float* __restrict__ out) {
    extern __shared__ float smem[];
    float* sin = smem;                                 // SIN_PAD floats
    unsigned long long* wsm2 = (unsigned long long*)(smem + SIN_PAD);  // NW pairs {w,w}

    const int tid = threadIdx.x + BX*(threadIdx.y + TY*threadIdx.z);

    const int x0 = blockIdx.x * TX;
    const int y0 = blockIdx.y * TY;
    const int zb = blockIdx.z;
    const int NBZ = (DOUT + TZ - 1) / TZ;   // 31
    const int b  = zb / NBZ;
    const int z0 = (zb % NBZ) * TZ;

    // cooperative load: input tile (guarded for grid edge)
    {
        const size_t rowstride = (size_t)DGRID * 3;        // 384
        for (int i = tid; i < SIN_FLOATS; i += NTHREADS) {
            int zz = i / SPLANE;
            int r  = i - zz * SPLANE;
            int yy = r / SXF;
            int xc = r - yy * SXF;       // flat x*3+c within tile
            int gz = z0 + zz;
            int gy = y0 + yy;
            int gxc = x0 * 3 + xc;       // flat x*3+c global
            float v = 0.f;
            if (gz < DGRID && gy < DGRID && gxc < (int)rowstride) {
                v = g_dense[(((size_t)b*DGRID + gz)*DGRID + gy)*rowstride + gxc];
            }
            sin[i] = v;
        }
        // weights duplicated into broadcast pairs {w, w}
        for (int i = tid; i < NW; i += NTHREADS) {
            float v = g_wc[i];
            wsm2[i] = packf2(v, v);
        }
    }
    __syncthreads();

    unsigned long long acc2[RX/2][COUT];   // packed over adjacent x-outputs
    #pragma unroll
    for (int j2 = 0; j2 < RX/2; j2++)
        #pragma unroll
        for (int c = 0; c < COUT; c++) acc2[j2][c] = 0ull;

    const int xoff = threadIdx.x * (RX * 3);   // float offset of this thread's x window

    for (int kz = 0; kz < KC; kz++) {
        for (int ky = 0; ky < KC; ky++) {
            const float* rp = &sin[((threadIdx.z + kz)*SY + (threadIdx.y + ky))*SXF + xoff];
            float r[(RX + 5) * 3];             // 39 floats
            #pragma unroll
            for (int v = 0; v < (RX + 5) * 3; v++) r[v] = rp[v];

            const unsigned long long* wrow = wsm2 + (kz*KC + ky)*KC*9;

            #pragma unroll
            for (int ci = 0; ci < CIN; ci++) {
                // pack sliding pairs {x[m], x[m+1]} for this input channel
                unsigned long long P[RX + 4];  // m = 0..11
                #pragma unroll
                for (int m = 0; m < RX + 4; m++)
                    P[m] = packf2(r[m*3 + ci], r[(m+1)*3 + ci]);

                #pragma unroll
                for (int kx = 0; kx < KC; kx++) {
                    const unsigned long long* wp = wrow + kx*9 + ci*3;
                    unsigned long long w0 = wp[0], w1 = wp[1], w2 = wp[2];
                    #pragma unroll
                    for (int j2 = 0; j2 < RX/2; j2++) {
                        unsigned long long xv = P[2*j2 + kx];
                        acc2[j2][0] = ffma2(xv, w0, acc2[j2][0]);
                        acc2[j2][1] = ffma2(xv, w1, acc2[j2][1]);
                        acc2[j2][2] = ffma2(xv, w2, acc2[j2][2]);
                    }
                }
            }
        }
    }

    // epilogue: bias + relu + store
    const float bb0 = b3[0], bb1 = b3[1], bb2 = b3[2];
    const int oz = z0 + threadIdx.z;
    const int oy = y0 + threadIdx.y;
    if (oz < DOUT && oy < DOUT) {
        const int oxb = x0 + threadIdx.x * RX;
        size_t rowbase = (((size_t)b*DOUT + oz)*DOUT + oy) * (size_t)DOUT * 3;
        #pragma unroll
        for (int j2 = 0; j2 < RX/2; j2++) {
            float a0[COUT], a1[COUT];
            #pragma unroll
            for (int c = 0; c < COUT; c++) unpackf2(acc2[j2][c], a0[c], a1[c]);

            int ox = oxb + 2*j2;
            if (ox < DOUT) {
                size_t o = rowbase + (size_t)ox * 3;
                out[o + 0] = fmaxf(a0[0] + bb0, 0.f);
                out[o + 1] = fmaxf(a0[1] + bb1, 0.f);
                out[o + 2] = fmaxf(a0[2] + bb2, 0.f);
            }
            if (ox + 1 < DOUT) {
                size_t o = rowbase + (size_t)(ox + 1) * 3;
                out[o + 0] = fmaxf(a1[0] + bb0, 0.f);
                out[o + 1] = fmaxf(a1[1] + bb1, 0.f);
                out[o + 2] = fmaxf(a1[2] + bb2, 0.f);
            }
        }
    }
}

// ---------------- launch ----------------
extern "C" void kernel_launch(void* const* d_in, const int* in_sizes, int n_in,
                              void* d_out, int out_size) {
    const int*   coords = (const int*)  d_in[0];
    const float* voxels = (const float*)d_in[1];
    const float* W1     = (const float*)d_in[2];
    const float* W2     = (const float*)d_in[3];
    const float* W3     = (const float*)d_in[4];
    const float* b3     = (const float*)d_in[5];
    float*       out    = (float*)d_out;

    const int n = in_sizes[0] / 4;

    // compose weights (tiny)
    compose_w12_kernel<<< (4*4*4*3*5 + 255)/256, 256 >>>(W1, W2);
    compose_wc_kernel<<< (NW + 255)/256, 256 >>>(W3);

    // zero the dense grid
    void* densep = nullptr;
    cudaGetSymbolAddress(&densep, g_dense);
    cudaMemsetAsync(densep, 0, (size_t)BATCH*DGRID*DGRID*DGRID*3*sizeof(float));

    // scatter sparse voxels
    scatter_kernel<<< (n + 255)/256, 256 >>>(coords, voxels, n);

    // fused conv
    const size_t smem_bytes = (size_t)SMEM_FLOATS * sizeof(float);
    cudaFuncSetAttribute(conv6_kernel,
                         cudaFuncAttributeMaxDynamicSharedMemorySize,
                         (int)smem_bytes);
    dim3 block(BX, TY, TZ);
    dim3 grid((DOUT + TX - 1)/TX,          // 4
              (DOUT + TY - 1)/TY,          // 16
              BATCH * ((DOUT + TZ - 1)/TZ));  // 62
    conv6_kernel<<<grid, block, smem_bytes>>>(b3, out);
}

// round 3
// speedup vs baseline: 1.0456x; 1.0456x over previous
#include <cuda_runtime.h>
#include <cuda_bf16.h>
#include <math.h>

// Problem constants
#define BATCH 2
#define DGRID 128
#define DOUT  123
#define KC    6
#define CIN   3
#define COUT  3

// Tiling: block (4,8,4) = 128 threads; each thread: 8 x-outputs, 1 z, both batches
#define BX 4
#define TY 8
#define TZ 4
#define RX 8
#define TX (BX*RX)             // 32
#define NTHREADS (BX*TY*TZ)    // 128

// smem input tile (float2 = {b0,b1} pairs), layout [z][y][x*3+ci]
#define SZ (TZ+5)              // 9
#define SY (TY+5)              // 13
#define SXU 111                // used f2 per row = (TX+5)*3
#define SROW 114               // padded row stride (f2), 16B-aligned
#define SPLANE (SY*SROW)       // 1482
#define SMEM_F2 (SZ*SPLANE)    // 13338 f2 = 106,704 B
#define NW (KC*KC*KC*CIN*COUT) // 1944

typedef unsigned long long ull;

// ---------------- device scratch ----------------
__device__ float2 g_dense2[(size_t)DGRID*DGRID*DGRID*3];   // 50.3 MB, batch-paired
__device__ float  g_w12[4*4*4*3*5];
__device__ float2 g_wc2[NW];    // composed weights as {w,w} pairs, [kz][ky][kx][ci][co]

// ---------------- f32x2 helpers ----------------
__device__ __forceinline__ ull ffma2(ull a, ull b, ull c) {
    ull d;
    asm("fma.rn.f32x2 %0, %1, %2, %3;" : "=l"(d) : "l"(a), "l"(b), "l"(c));
    return d;
}
__device__ __forceinline__ void unpackf2(ull v, float& lo, float& hi) {
    asm("mov.b64 {%0, %1}, %2;" : "=f"(lo), "=f"(hi) : "l"(v));
}

// ---------------- weight composition ----------------
__global__ void compose_w12_kernel(const float* __restrict__ W1,
                                   const float* __restrict__ W2) {
    int idx = blockIdx.x * blockDim.x + threadIdx.x;
    if (idx >= 4*4*4*3*5) return;
    int c5 = idx % 5; int t = idx / 5;
    int ci = t % 3;   t /= 3;
    int kx = t % 4;   t /= 4;
    int ky = t % 4;   int kz = t / 4;
    float s = 0.f;
    for (int az = 0; az < 2; az++) {
        int bz = kz - az; if (bz < 0 || bz > 2) continue;
        for (int ay = 0; ay < 2; ay++) {
            int by = ky - ay; if (by < 0 || by > 2) continue;
            for (int ax = 0; ax < 2; ax++) {
                int bx = kx - ax; if (bx < 0 || bx > 2) continue;
                const float* w1 = W1 + (((az*2 + ay)*2 + ax)*3 + ci)*9;
                const float* w2 = W2 + ((bz*3 + by)*3 + bx)*9*5;
                #pragma unroll
                for (int m = 0; m < 9; m++)
                    s += w1[m] * w2[m*5 + c5];
            }
        }
    }
    g_w12[idx] = s;
}

__global__ void compose_wc_kernel(const float* __restrict__ W3) {
    int idx = blockIdx.x * blockDim.x + threadIdx.x;
    if (idx >= NW) return;
    int co = idx % 3; int t = idx / 3;
    int ci = t % 3;   t /= 3;
    int kx = t % 6;   t /= 6;
    int ky = t % 6;   int kz = t / 6;
    float s = 0.f;
    for (int dz = 0; dz < 4; dz++) {
        int ez = kz - dz; if (ez < 0 || ez > 2) continue;
        for (int dy = 0; dy < 4; dy++) {
            int ey = ky - dy; if (ey < 0 || ey > 2) continue;
            for (int dx = 0; dx < 4; dx++) {
                int ex = kx - dx; if (ex < 0 || ex > 2) continue;
                const float* w12 = g_w12 + (((dz*4 + dy)*4 + dx)*3 + ci)*5;
                const float* w3  = W3 + ((ez*3 + ey)*3 + ex)*5*3;
                #pragma unroll
                for (int c5 = 0; c5 < 5; c5++)
                    s += w12[c5] * w3[c5*3 + co];
            }
        }
    }
    g_wc2[idx] = make_float2(s, s);
}

// ---------------- scatter (into batch-paired grid) ----------------
__global__ void scatter_kernel(const int* __restrict__ coords,
                               const float* __restrict__ voxels, int n) {
    int i = blockIdx.x * blockDim.x + threadIdx.x;
    if (i >= n) return;
    int b = coords[4*i + 0];
    int z = coords[4*i + 1];
    int y = coords[4*i + 2];
    int x = coords[4*i + 3];
    size_t base = (((size_t)z*DGRID + y)*DGRID + x) * 3;   // f2 index
    float* g = (float*)g_dense2;
    atomicAdd(&g[(base + 0)*2 + b], voxels[3*i + 0]);
    atomicAdd(&g[(base + 1)*2 + b], voxels[3*i + 1]);
    atomicAdd(&g[(base + 2)*2 + b], voxels[3*i + 2]);
}

// ---------------- fused 6x6x6 conv, batch-paired FFMA2 ----------------
__global__ __launch_bounds__(NTHREADS, 2)
void conv6_kernel(const float* __restrict__ b3, float* __restrict__ out) {
    extern __shared__ float2 smem[];   // SMEM_F2 pairs

    const int tx = threadIdx.x;        // 0..3
    const int ty = threadIdx.y;        // 0..7
    const int tz = threadIdx.z;        // 0..3
    const int tid = tx + BX*(ty + TY*tz);

    const int x0 = blockIdx.x * TX;    // voxel x base
    const int y0 = blockIdx.y * TY;
    const int z0 = blockIdx.z * TZ;

    // ---- cooperative load: 9 x 13 x 111 f2 tile, zero-padded at grid edges ----
    {
        const int xf0 = x0 * 3;                     // f2 base within global row (384 wide)
        for (int i = tid; i < SZ*SY*SXU; i += NTHREADS) {
            int zz = i / (SY*SXU);
            int r  = i - zz*(SY*SXU);
            int yy = r / SXU;
            int xc = r - yy*SXU;
            int gz = z0 + zz;
            int gy = y0 + yy;
            int gxc = xf0 + xc;
            float2 v = make_float2(0.f, 0.f);
            if (gz < DGRID && gy < DGRID && gxc < DGRID*3)
                v = g_dense2[((size_t)gz*DGRID + gy)*(DGRID*3) + gxc];
            smem[(zz*SY + yy)*SROW + xc] = v;
        }
    }
    __syncthreads();

    ull acc[RX][COUT];
    #pragma unroll
    for (int j = 0; j < RX; j++)
        #pragma unroll
        for (int c = 0; c < COUT; c++) acc[j][c] = 0ull;

    const float2* __restrict__ wc = g_wc2;

    #pragma unroll 1
    for (int kz = 0; kz < KC; kz++) {
        #pragma unroll 1
        for (int ky = 0; ky < KC; ky++) {
            // contiguous row segment: 40 f2 (39 used) as 20 float4 loads
            const float4* rp = (const float4*)&smem[((tz + kz)*SY + (ty + ky))*SROW + tx*(RX*3)];
            union { float4 q[20]; ull p[40]; } r;
            #pragma unroll
            for (int i = 0; i < 20; i++) r.q[i] = rp[i];

            const float2* wrow = wc + (kz*KC + ky)*KC*CIN*COUT;

            #pragma unroll
            for (int kx = 0; kx < KC; kx++) {
                #pragma unroll
                for (int ci = 0; ci < CIN; ci++) {
                    const float2* wp = wrow + (kx*CIN + ci)*COUT;
                    float2 wf0 = __ldg(wp + 0);
                    float2 wf1 = __ldg(wp + 1);
                    float2 wf2 = __ldg(wp + 2);
                    ull w0, w1, w2;
                    asm("mov.b64 %0, {%1, %2};" : "=l"(w0) : "f"(wf0.x), "f"(wf0.y));
                    asm("mov.b64 %0, {%1, %2};" : "=l"(w1) : "f"(wf1.x), "f"(wf1.y));
                    asm("mov.b64 %0, {%1, %2};" : "=l"(w2) : "f"(wf2.x), "f"(wf2.y));
                    #pragma unroll
                    for (int j = 0; j < RX; j++) {
                        ull xv = r.p[3*(j + kx) + ci];
                        acc[j][0] = ffma2(xv, w0, acc[j][0]);
                        acc[j][1] = ffma2(xv, w1, acc[j][1]);
                        acc[j][2] = ffma2(xv, w2, acc[j][2]);
                    }
                }
            }
        }
    }

    // ---- epilogue: bias + relu + store both batches ----
    const float bb[3] = { b3[0], b3[1], b3[2] };
    const int oz = z0 + tz;
    const int oy = y0 + ty;
    if (oz < DOUT && oy < DOUT) {
        const int oxb = x0 + tx*RX;
        const size_t bstride = (size_t)DOUT*DOUT*DOUT*3;
        size_t rowbase = (((size_t)oz*DOUT + oy)) * (size_t)DOUT * 3;
        #pragma unroll
        for (int j = 0; j < RX; j++) {
            int ox = oxb + j;
            if (ox < DOUT) {
                size_t o = rowbase + (size_t)ox*3;
                #pragma unroll
                for (int c = 0; c < COUT; c++) {
                    float v0, v1;
                    unpackf2(acc[j][c], v0, v1);
                    out[o + c]           = fmaxf(v0 + bb[c], 0.f);
                    out[bstride + o + c] = fmaxf(v1 + bb[c], 0.f);
                }
            }
        }
    }
}

// ---------------- launch ----------------
extern "C" void kernel_launch(void* const* d_in, const int* in_sizes, int n_in,
                              void* d_out, int out_size) {
    const int*   coords = (const int*)  d_in[0];
    const float* voxels = (const float*)d_in[1];
    const float* W1     = (const float*)d_in[2];
    const float* W2     = (const float*)d_in[3];
    const float* W3     = (const float*)d_in[4];
    const float* b3     = (const float*)d_in[5];
    float*       out    = (float*)d_out;

    const int n = in_sizes[0] / 4;

    compose_w12_kernel<<< (4*4*4*3*5 + 255)/256, 256 >>>(W1, W2);
    compose_wc_kernel<<< (NW + 255)/256, 256 >>>(W3);

    void* densep = nullptr;
    cudaGetSymbolAddress(&densep, g_dense2);
    cudaMemsetAsync(densep, 0, (size_t)DGRID*DGRID*DGRID*3*sizeof(float2));

    scatter_kernel<<< (n + 255)/256, 256 >>>(coords, voxels, n);

    const size_t smem_bytes = (size_t)SMEM_F2 * sizeof(float2);   // 106,704 B
    cudaFuncSetAttribute(conv6_kernel,
                         cudaFuncAttributeMaxDynamicSharedMemorySize,
                         (int)smem_bytes);
    dim3 block(BX, TY, TZ);
    dim3 grid((DOUT + TX - 1)/TX,        // 4
              (DOUT + TY - 1)/TY,        // 16
              (DOUT + TZ - 1)/TZ);       // 31
    conv6_kernel<<<grid, block, smem_bytes>>>(b3, out);
}